// round 14
// baseline (speedup 1.0000x reference)
#include <cuda_runtime.h>
#include <cuda_fp16.h>

#define N_NODES 50000
#define N_EDGES 1600000
#define HID 256
#define SCAN_B 196   // ceil(N_NODES/256)

// ---------------- device scratch (static, no allocs) ----------------
__device__ float4   g_agb[N_NODES*HID/4];   // aggr output (tf32 bits) / layer1 aggr (fp32)
__device__ __half   g_h16a[N_NODES*HID];    // h fp16 buffer A
__device__ __half   g_h16b[N_NODES*HID];    // h fp16 buffer B
__device__ unsigned g_W2t[65536];           // W2 in tf32 fragment order
__device__ int      g_deg[N_NODES];
__device__ int      g_rowptr[N_NODES + 1];
__device__ int      g_rank[N_EDGES];        // edge's rank within its dst bucket
__device__ int      g_csrs[N_EDGES];        // src node, grouped by dst
__device__ uint4    g_eah[N_EDGES];         // edge attrs: 8 packed halfs, CSR order
__device__ unsigned long long g_scanst[SCAN_B];  // decoupled-lookback state
__device__ int      g_flag;                 // 1 = edge_index int64, 0 = int32

__device__ __forceinline__ void red_add_v2(float* a, float x, float y) {
    asm volatile("red.global.add.v2.f32 [%0], {%1,%2};"
                 :: "l"(a), "f"(x), "f"(y) : "memory");
}
__device__ __forceinline__ unsigned to_tf32(float v) {
    unsigned r;
    asm("cvt.rna.tf32.f32 %0, %1;" : "=r"(r) : "f"(v));
    return r;
}
__device__ __forceinline__ int edge_src(const void* ei, int i) {
    return g_flag ? (int)((const long long*)ei)[i] : ((const int*)ei)[i];
}
__device__ __forceinline__ int edge_dst(const void* ei, int i) {
    return g_flag ? (int)((const long long*)ei)[N_EDGES + i]
                  : ((const int*)ei)[N_EDGES + i];
}

// ------- fused prep: detect dtype, W2->tf32 frags, zero deg/agb/scan -------
__global__ void k_prep(const void* ei, const float* __restrict__ W) {
    int idx = blockIdx.x * 256 + threadIdx.x;   // 65536 threads
    if (idx == 0) {
        const long long* p = (const long long*)ei;
        int is64 = 1;
        for (int i = 0; i < 64; i++) {
            long long v = p[i];
            if (v < 0 || v >= N_NODES) { is64 = 0; break; }
        }
        g_flag = is64;
    }
    {   // W2 fragment table
        int slot = idx & 1;
        int l    = (idx >> 1) & 31;
        int ks   = (idx >> 6) & 31;
        int ct   = idx >> 11;
        int k = ks * 8 + (l & 3) + slot * 4;
        int n = ct * 8 + (l >> 2);
        g_W2t[idx] = to_tf32(W[k * HID + n]);
    }
    if (idx < N_NODES) g_deg[idx] = 0;
    if (idx < SCAN_B)  g_scanst[idx] = 0ULL;
    float* ag = (float*)g_agb;
    for (int i = idx; i < 2 * N_NODES; i += 65536) ag[i] = 0.f;
}

// ---------------- CSR build ----------------
// hist records each edge's rank within its dst bucket (atomicAdd return).
// 2 edges per thread for MLP.
__global__ void k_hist(const void* ei) {
    int i0 = 2 * (blockIdx.x * blockDim.x + threadIdx.x);
    if (i0 >= N_EDGES) return;
    int d0 = edge_dst(ei, i0);
    int d1 = edge_dst(ei, i0 + 1);
    g_rank[i0]     = atomicAdd(&g_deg[d0], 1);
    g_rank[i0 + 1] = atomicAdd(&g_deg[d1], 1);
}

// single-pass scan via decoupled lookback: deg -> rowptr
__global__ void k_scan1() {
    __shared__ int sm[256];
    __shared__ int s_prefix;
    int t = threadIdx.x;
    int bid = blockIdx.x;
    int n = bid * 256 + t;
    int v = (n < N_NODES) ? g_deg[n] : 0;
    sm[t] = v;
    __syncthreads();
    for (int o = 1; o < 256; o <<= 1) {
        int u = (t >= o) ? sm[t - o] : 0;
        __syncthreads();
        sm[t] += u;
        __syncthreads();
    }
    int total = sm[255];
    if (t == 0) {
        unsigned long long st;
        if (bid == 0) {
            st = (2ULL << 32) | (unsigned)total;
            atomicExch(&g_scanst[0], st);
            s_prefix = 0;
        } else {
            st = (1ULL << 32) | (unsigned)total;
            atomicExch(&g_scanst[bid], st);
            int pref = 0;
            int p = bid - 1;
            while (true) {
                unsigned long long s2;
                do { s2 = atomicAdd(&g_scanst[p], 0ULL); } while ((s2 >> 32) == 0ULL);
                pref += (int)(unsigned)s2;
                if ((s2 >> 32) == 2ULL) break;
                p--;
            }
            atomicExch(&g_scanst[bid], (2ULL << 32) | (unsigned)(total + pref));
            s_prefix = pref;
        }
    }
    __syncthreads();
    int ex = s_prefix + sm[t] - v;   // exclusive prefix
    if (n < N_NODES) g_rowptr[n] = ex;
    if (bid == SCAN_B - 1 && t == 255) g_rowptr[N_NODES] = N_EDGES;
}

// ---------------- fused fill + layer1 scatter (2 edges/thread) -------------
__global__ void k_fillscat(const void* ei, const float* __restrict__ ea,
                           const float* __restrict__ x,
                           const float* __restrict__ We1,
                           const float* __restrict__ be1) {
    int e0 = 2 * (blockIdx.x * blockDim.x + threadIdx.x);
    if (e0 >= N_EDGES) return;
    int e1 = e0 + 1;
    // issue all index loads up front
    int s0 = edge_src(ei, e0), d0 = edge_dst(ei, e0);
    int s1 = edge_src(ei, e1), d1 = edge_dst(ei, e1);
    int rp0 = g_rowptr[d0], rk0 = g_rank[e0];
    int rp1 = g_rowptr[d1], rk1 = g_rank[e1];
    float a0[7], a1[7];
    const float* ap = ea + (size_t)e0 * 7;
#pragma unroll
    for (int k = 0; k < 7; k++) a0[k] = ap[k];
#pragma unroll
    for (int k = 0; k < 7; k++) a1[k] = ap[7 + k];
    float x00 = x[2 * s0 + 0], x01 = x[2 * s0 + 1];
    float x10 = x[2 * s1 + 0], x11 = x[2 * s1 + 1];

    int pos0 = rp0 + rk0, pos1 = rp1 + rk1;
    g_csrs[pos0] = s0;
    g_csrs[pos1] = s1;
    uint4 v0, v1;
    __half2* p0 = (__half2*)&v0;
    __half2* p1 = (__half2*)&v1;
    p0[0] = __floats2half2_rn(a0[0], a0[1]);
    p0[1] = __floats2half2_rn(a0[2], a0[3]);
    p0[2] = __floats2half2_rn(a0[4], a0[5]);
    p0[3] = __floats2half2_rn(a0[6], 0.f);
    p1[0] = __floats2half2_rn(a1[0], a1[1]);
    p1[1] = __floats2half2_rn(a1[2], a1[3]);
    p1[2] = __floats2half2_rn(a1[4], a1[5]);
    p1[3] = __floats2half2_rn(a1[6], 0.f);
    g_eah[pos0] = v0;
    g_eah[pos1] = v1;

    float w0c0 = __ldg(&be1[0]), w0c1 = __ldg(&be1[1]);
    float m00 = w0c0, m01 = w0c1, m10 = w0c0, m11 = w0c1;
#pragma unroll
    for (int k = 0; k < 7; k++) {
        float wk0 = __ldg(&We1[k * 2 + 0]);
        float wk1 = __ldg(&We1[k * 2 + 1]);
        m00 += a0[k] * wk0; m01 += a0[k] * wk1;
        m10 += a1[k] * wk0; m11 += a1[k] * wk1;
    }
    m00 = fmaxf(x00 + m00, 0.f); m01 = fmaxf(x01 + m01, 0.f);
    m10 = fmaxf(x10 + m10, 0.f); m11 = fmaxf(x11 + m11, 0.f);
    red_add_v2(((float*)g_agb) + 2 * d0, m00, m01);
    red_add_v2(((float*)g_agb) + 2 * d1, m10, m11);
}

// ---------------- layer 1 nn -> fp16 ----------------
__global__ void k_layer1nn(const float* __restrict__ x,
                           const float* __restrict__ W1,
                           const float* __restrict__ b1) {
    int n = blockIdx.x;
    int c = threadIdx.x;
    const float* ag = (const float*)g_agb;
    float a0 = x[2 * n + 0] + ag[2 * n + 0];
    float a1 = x[2 * n + 1] + ag[2 * n + 1];
    float v = b1[c] + a0 * W1[c] + a1 * W1[HID + c];
    g_h16a[n * HID + c] = __float2half(fmaxf(v, 0.f));
}

// ---------------- layers 2/3 aggregation: rolling software pipeline --------
// One warp/node, 8 ch/lane. Gathers for batch n+1 issue while batch n's
// second half computes; h-register slots recycled right after consumption.
__device__ __forceinline__ void aggr_edge_acc(
    __half2 macc[4], const __half2 wh[7][4], const __half2 bh[4],
    uint4 ua, uint4 uh)
{
    const __half2* ap = (const __half2*)&ua;   // (a0,a1)(a2,a3)(a4,a5)(a6,_)
    __half2 a0 = __low2half2(ap[0]),  a1 = __high2half2(ap[0]);
    __half2 a2 = __low2half2(ap[1]),  a3 = __high2half2(ap[1]);
    __half2 a4 = __low2half2(ap[2]),  a5 = __high2half2(ap[2]);
    __half2 a6 = __low2half2(ap[3]);
    const __half2* h2 = (const __half2*)&uh;   // 8 fp16 channels
    __half2 zero = __float2half2_rn(0.f);
#pragma unroll
    for (int c = 0; c < 4; c++) {
        __half2 m = bh[c];
        m = __hfma2(a0, wh[0][c], m);
        m = __hfma2(a1, wh[1][c], m);
        m = __hfma2(a2, wh[2][c], m);
        m = __hfma2(a3, wh[3][c], m);
        m = __hfma2(a4, wh[4][c], m);
        m = __hfma2(a5, wh[5][c], m);
        m = __hfma2(a6, wh[6][c], m);
        m = __hadd2(m, h2[c]);
        m = __hmax2(m, zero);
        macc[c] = __hadd2(macc[c], m);
    }
}

__device__ __forceinline__ void flush_macc(float* accf, const __half2 macc[4]) {
#pragma unroll
    for (int c = 0; c < 4; c++) {
        float2 f = __half22float2(macc[c]);
        accf[2 * c + 0] += f.x;
        accf[2 * c + 1] += f.y;
    }
}

__global__ void __launch_bounds__(256, 2)
k_aggr(int useB, const float* __restrict__ We2, const float* __restrict__ be2) {
    const __half* hin = useB ? g_h16b : g_h16a;
    int node = (blockIdx.x * blockDim.x + threadIdx.x) >> 5;
    if (node >= N_NODES) return;
    int lane = threadIdx.x & 31;
    int ch = lane * 8;

    __half2 wh[7][4];
#pragma unroll
    for (int k = 0; k < 7; k++) {
        float4 lo = *(const float4*)&We2[k * HID + ch];
        float4 hi = *(const float4*)&We2[k * HID + ch + 4];
        wh[k][0] = __floats2half2_rn(lo.x, lo.y);
        wh[k][1] = __floats2half2_rn(lo.z, lo.w);
        wh[k][2] = __floats2half2_rn(hi.x, hi.y);
        wh[k][3] = __floats2half2_rn(hi.z, hi.w);
    }
    __half2 bh[4];
    {
        float4 lo = *(const float4*)&be2[ch];
        float4 hi = *(const float4*)&be2[ch + 4];
        bh[0] = __floats2half2_rn(lo.x, lo.y);
        bh[1] = __floats2half2_rn(lo.z, lo.w);
        bh[2] = __floats2half2_rn(hi.x, hi.y);
        bh[3] = __floats2half2_rn(hi.z, hi.w);
    }

    float accf[8];
    {
        uint4 uh = *(const uint4*)&hin[node * HID + ch];
        const __half2* h2 = (const __half2*)&uh;
#pragma unroll
        for (int c = 0; c < 4; c++) {
            float2 f = __half22float2(h2[c]);
            accf[2 * c + 0] = f.x;
            accf[2 * c + 1] = f.y;
        }
    }

    int beg = g_rowptr[node], end = g_rowptr[node + 1];
    int nb = (end - beg) >> 3;      // full 8-edge batches
    int j = beg;

    uint4 h0, h1, h2, h3, h4, h5, h6, h7;
    if (nb > 0) {
        int s0 = g_csrs[j + 0], s1 = g_csrs[j + 1], s2 = g_csrs[j + 2], s3 = g_csrs[j + 3];
        int s4 = g_csrs[j + 4], s5 = g_csrs[j + 5], s6 = g_csrs[j + 6], s7 = g_csrs[j + 7];
        h0 = *(const uint4*)&hin[s0 * HID + ch];
        h1 = *(const uint4*)&hin[s1 * HID + ch];
        h2 = *(const uint4*)&hin[s2 * HID + ch];
        h3 = *(const uint4*)&hin[s3 * HID + ch];
        h4 = *(const uint4*)&hin[s4 * HID + ch];
        h5 = *(const uint4*)&hin[s5 * HID + ch];
        h6 = *(const uint4*)&hin[s6 * HID + ch];
        h7 = *(const uint4*)&hin[s7 * HID + ch];
    }

    for (int b = 0; b < nb; b++, j += 8) {
        bool more = (b + 1 < nb);
        // compute edges 0-3 of this batch
        {
            uint4 a0 = g_eah[j + 0], a1 = g_eah[j + 1];
            uint4 a2 = g_eah[j + 2], a3 = g_eah[j + 3];
            __half2 macc[4];
            macc[0] = macc[1] = macc[2] = macc[3] = __float2half2_rn(0.f);
            aggr_edge_acc(macc, wh, bh, a0, h0);
            aggr_edge_acc(macc, wh, bh, a1, h1);
            aggr_edge_acc(macc, wh, bh, a2, h2);
            aggr_edge_acc(macc, wh, bh, a3, h3);
            flush_macc(accf, macc);
        }
        // recycle slots 0-3: issue next batch's first-half gathers
        if (more) {
            int t0 = g_csrs[j + 8], t1 = g_csrs[j + 9];
            int t2 = g_csrs[j + 10], t3 = g_csrs[j + 11];
            h0 = *(const uint4*)&hin[t0 * HID + ch];
            h1 = *(const uint4*)&hin[t1 * HID + ch];
            h2 = *(const uint4*)&hin[t2 * HID + ch];
            h3 = *(const uint4*)&hin[t3 * HID + ch];
        }
        // compute edges 4-7 (their gathers were issued one batch ago)
        {
            uint4 a4 = g_eah[j + 4], a5 = g_eah[j + 5];
            uint4 a6 = g_eah[j + 6], a7 = g_eah[j + 7];
            __half2 macc[4];
            macc[0] = macc[1] = macc[2] = macc[3] = __float2half2_rn(0.f);
            aggr_edge_acc(macc, wh, bh, a4, h4);
            aggr_edge_acc(macc, wh, bh, a5, h5);
            aggr_edge_acc(macc, wh, bh, a6, h6);
            aggr_edge_acc(macc, wh, bh, a7, h7);
            flush_macc(accf, macc);
        }
        // recycle slots 4-7
        if (more) {
            int t4 = g_csrs[j + 12], t5 = g_csrs[j + 13];
            int t6 = g_csrs[j + 14], t7 = g_csrs[j + 15];
            h4 = *(const uint4*)&hin[t4 * HID + ch];
            h5 = *(const uint4*)&hin[t5 * HID + ch];
            h6 = *(const uint4*)&hin[t6 * HID + ch];
            h7 = *(const uint4*)&hin[t7 * HID + ch];
        }
    }

    // tail (<8 edges)
    for (; j < end; j++) {
        int sj = g_csrs[j];
        uint4 a = g_eah[j];
        uint4 h = *(const uint4*)&hin[sj * HID + ch];
        __half2 macc[4];
        macc[0] = macc[1] = macc[2] = macc[3] = __float2half2_rn(0.f);
        aggr_edge_acc(macc, wh, bh, a, h);
        flush_macc(accf, macc);
    }

    unsigned* outp = (unsigned*)g_agb + node * HID + ch;
    *(uint4*)outp =
        make_uint4(to_tf32(accf[0]), to_tf32(accf[1]), to_tf32(accf[2]), to_tf32(accf[3]));
    *(uint4*)(outp + 4) =
        make_uint4(to_tf32(accf[4]), to_tf32(accf[5]), to_tf32(accf[6]), to_tf32(accf[7]));
}

// ---------------- tf32 tensor-core GEMM ----------------
__global__ void __launch_bounds__(256)
k_gemm_tc(int layer, const float* __restrict__ b) {
    const unsigned* A = (const unsigned*)g_agb;   // tf32 bits, row-major
    __half* hout = (layer == 2) ? g_h16b : g_h16a;

    __shared__ unsigned As[8 * 4 * 4 * 32];   // [mt][ks][slot][lane]

    int tid = threadIdx.x;
    int lane = tid & 31;
    int warp = tid >> 5;
    int wr = warp >> 1;
    int wc = warp & 1;
    int rowBase = blockIdx.y * 128;
    int colBase16 = blockIdx.x * 16;

    float acc[2][8][4];
#pragma unroll
    for (int i = 0; i < 2; i++)
#pragma unroll
        for (int j = 0; j < 8; j++)
#pragma unroll
            for (int k = 0; k < 4; k++) acc[i][j][k] = 0.f;

    int a_c0 = tid & 7;
    int a_row0 = tid >> 3;
    int a_ks = a_c0 >> 1;
    int a_slot_hi = (a_c0 & 1) << 1;

    for (int kt = 0; kt < HID; kt += 32) {
#pragma unroll
        for (int i = 0; i < 4; i++) {
            int row = a_row0 + 32 * i;
            int grow = rowBase + row;
            uint4 v = make_uint4(0u, 0u, 0u, 0u);
            if (grow < N_NODES)
                v = *(const uint4*)&A[grow * HID + kt + a_c0 * 4];
            int rr = row & 15, mt = row >> 4;
            int slot = (rr >> 3) | a_slot_hi;
            *(uint4*)&As[(((mt * 4 + a_ks) * 4 + slot) * 32 + (rr & 7) * 4)] = v;
        }
        __syncthreads();

        uint2 bf[8];
#pragma unroll
        for (int ntl = 0; ntl < 8; ntl++) {
            int ct = colBase16 + wc * 8 + ntl;
            bf[ntl] = *(const uint2*)&g_W2t[((ct * 32 + (kt >> 3)) * 32 + lane) * 2];
        }
#pragma unroll
        for (int ks = 0; ks < 4; ks++) {
            uint2 bfn[8];
            if (ks < 3) {
#pragma unroll
                for (int ntl = 0; ntl < 8; ntl++) {
                    int ct = colBase16 + wc * 8 + ntl;
                    bfn[ntl] = *(const uint2*)&g_W2t[((ct * 32 + (kt >> 3) + ks + 1) * 32 + lane) * 2];
                }
            }
            unsigned af[2][4];
#pragma unroll
            for (int mtl = 0; mtl < 2; mtl++) {
                int mt = wr * 2 + mtl;
#pragma unroll
                for (int s = 0; s < 4; s++)
                    af[mtl][s] = As[((mt * 4 + ks) * 4 + s) * 32 + lane];
            }
#pragma unroll
            for (int mtl = 0; mtl < 2; mtl++)
#pragma unroll
                for (int ntl = 0; ntl < 8; ntl++) {
                    asm volatile(
                        "mma.sync.aligned.m16n8k8.row.col.f32.tf32.tf32.f32 "
                        "{%0,%1,%2,%3}, {%4,%5,%6,%7}, {%8,%9}, {%0,%1,%2,%3};"
                        : "+f"(acc[mtl][ntl][0]), "+f"(acc[mtl][ntl][1]),
                          "+f"(acc[mtl][ntl][2]), "+f"(acc[mtl][ntl][3])
                        : "r"(af[mtl][0]), "r"(af[mtl][1]),
                          "r"(af[mtl][2]), "r"(af[mtl][3]),
                          "r"(bf[ntl].x), "r"(bf[ntl].y));
                }
            if (ks < 3) {
#pragma unroll
                for (int ntl = 0; ntl < 8; ntl++) bf[ntl] = bfn[ntl];
            }
        }
        __syncthreads();
    }

    int gid = lane >> 2;
    int tig = lane & 3;
#pragma unroll
    for (int mtl = 0; mtl < 2; mtl++) {
        int row0 = rowBase + (wr * 2 + mtl) * 16 + gid;
#pragma unroll
        for (int ntl = 0; ntl < 8; ntl++) {
            int col = colBase16 * 8 + (wc * 8 + ntl) * 8 + tig * 2;
            float2 bv = *(const float2*)&b[col];
            if (row0 < N_NODES) {
                __half2 o = __floats2half2_rn(fmaxf(acc[mtl][ntl][0] + bv.x, 0.f),
                                              fmaxf(acc[mtl][ntl][1] + bv.y, 0.f));
                *(__half2*)&hout[row0 * HID + col] = o;
            }
            if (row0 + 8 < N_NODES) {
                __half2 o = __floats2half2_rn(fmaxf(acc[mtl][ntl][2] + bv.x, 0.f),
                                              fmaxf(acc[mtl][ntl][3] + bv.y, 0.f));
                *(__half2*)&hout[(row0 + 8) * HID + col] = o;
            }
        }
    }
}

// ---------------- final: sigmoid(h @ Wend + bend) ----------------
__global__ void k_final(const float* __restrict__ Wend,
                        const float* __restrict__ bend,
                        float* __restrict__ out) {
    int lane = threadIdx.x & 31;
    int warp = threadIdx.x >> 5;
    int n = blockIdx.x * 8 + warp;
    if (n >= N_NODES) return;
    float s = 0.f;
#pragma unroll
    for (int c = lane * 8; c < HID; c += 256) {
        uint4 uh = *(const uint4*)&g_h16a[n * HID + c];
        const __half2* h2 = (const __half2*)&uh;
        float4 w0 = *(const float4*)&Wend[c];
        float4 w1 = *(const float4*)&Wend[c + 4];
        float2 f0 = __half22float2(h2[0]);
        float2 f1 = __half22float2(h2[1]);
        float2 f2 = __half22float2(h2[2]);
        float2 f3 = __half22float2(h2[3]);
        s += f0.x * w0.x + f0.y * w0.y + f1.x * w0.z + f1.y * w0.w;
        s += f2.x * w1.x + f2.y * w1.y + f3.x * w1.z + f3.y * w1.w;
    }
#pragma unroll
    for (int o = 16; o; o >>= 1) s += __shfl_xor_sync(0xffffffffu, s, o);
    if (lane == 0) out[n] = 1.f / (1.f + __expf(-(s + bend[0])));
}

// ---------------- host ----------------
extern "C" void kernel_launch(void* const* d_in, const int* in_sizes, int n_in,
                              void* d_out, int out_size) {
    const float* x    = (const float*)d_in[0];
    const void*  ei   = d_in[1];
    const float* ea   = (const float*)d_in[2];
    const float* We1  = (const float*)d_in[3];
    const float* be1  = (const float*)d_in[4];
    const float* W1   = (const float*)d_in[5];
    const float* b1   = (const float*)d_in[6];
    const float* We2  = (const float*)d_in[7];
    const float* be2  = (const float*)d_in[8];
    const float* W2   = (const float*)d_in[9];
    const float* b2   = (const float*)d_in[10];
    const float* Wend = (const float*)d_in[11];
    const float* bend = (const float*)d_in[12];
    float* out = (float*)d_out;

    k_prep<<<256, 256>>>(ei, W2);                                       // 0
    k_hist<<<(N_EDGES / 2 + 255) / 256, 256>>>(ei);                     // 1
    k_scan1<<<SCAN_B, 256>>>();                                         // 2
    k_fillscat<<<(N_EDGES / 2 + 255) / 256, 256>>>(ei, ea, x, We1, be1);// 3
    k_layer1nn<<<N_NODES, 256>>>(x, W1, b1);                            // 4

    // layer 2
    k_aggr<<<(N_NODES * 32 + 255) / 256, 256>>>(0, We2, be2);           // 5
    k_gemm_tc<<<dim3(2, (N_NODES + 127) / 128), 256>>>(2, b2);

    // layer 3
    k_aggr<<<(N_NODES * 32 + 255) / 256, 256>>>(1, We2, be2);
    k_gemm_tc<<<dim3(2, (N_NODES + 127) / 128), 256>>>(3, b2);

    k_final<<<(N_NODES + 7) / 8, 256>>>(Wend, bend, out);
}